// round 4
// baseline (speedup 1.0000x reference)
#include <cuda_runtime.h>
#include <math.h>

// Problem constants
#define NYg    256
#define PMLc   20
#define PADc   22          // PML + FD_PAD
#define NP     300         // NYP == NXP
#define SXc    320         // padded row stride (floats)
#define Gc     4           // zero guard ring width
#define ARc    (NP + 2*Gc) // 308 rows allocated
#define Fc     (ARc*SXc)   // floats per field = 98560
#define NTc    250
#define NSHOTc 2
#define NSRCc  8
#define NRECc  64

#define DTc 0.0005f
#define Hc  5.0f

// Persistent-kernel config
#define NCTA 120
#define TPB  320
#define CPS  (NCTA/NSHOTc)  // 60 CTAs per shot
#define RPC  (NP/CPS)       // 5 rows per CTA
#define HR   (RPC+4)        // 9 psiy rows (owned + 2 halo each side)
#define CR   (RPC+8)        // 13 wfc column rows

// Per-shot fields: w0,w1,py0,py1 (psix in smem, zeta/wfm in regs). v2 -> field 8
__device__ float g_state[9*Fc];
__device__ float g_a[NP];
__device__ float g_b[NP];
__device__ unsigned g_arr[NCTA];    // one-time init barrier (equality, replay-safe)
__device__ unsigned g_sense;
__device__ unsigned g_step[NCTA];   // per-CTA completed-step counters

__device__ __forceinline__ int IDX(int y, int x) { return (y+Gc)*SXc + (x+Gc); }

__device__ __forceinline__ unsigned ld_rlx(const unsigned* p) {
    unsigned v;
    asm volatile("ld.relaxed.gpu.u32 %0, [%1];" : "=r"(v) : "l"(p));
    return v;
}
__device__ __forceinline__ void st_rlx(unsigned* p, unsigned v) {
    asm volatile("st.relaxed.gpu.u32 [%0], %1;" :: "l"(p), "r"(v) : "memory");
}
__device__ __forceinline__ void fence_gpu() {
    asm volatile("fence.acq_rel.gpu;" ::: "memory");
}

// One-time global barrier (equality on phase: replay-safe — stale values from a
// prior launch cannot equal the fresh phase until the owner stores it).
__device__ __forceinline__ void gbar(int cta, unsigned ph) {
    __syncthreads();
    if (cta == 0) {
        if (threadIdx.x >= 1 && threadIdx.x < NCTA) {
            while (ld_rlx(&g_arr[threadIdx.x]) != ph) { }
        }
        __syncthreads();
        if (threadIdx.x == 0) { fence_gpu(); st_rlx(&g_sense, ph); }
        __syncthreads();
    } else {
        if (threadIdx.x == 0) {
            fence_gpu();
            st_rlx(&g_arr[cta], ph);
            while (ld_rlx(&g_sense) != ph) { }
            fence_gpu();
        }
        __syncthreads();
    }
}

extern "C" __global__ void __launch_bounds__(TPB)
wave_kernel(const float* __restrict__ v,
            const float* __restrict__ amp,
            const void*  __restrict__ sloc,
            const void*  __restrict__ rloc,
            float* __restrict__ out)
{
    const int cta = blockIdx.x, tid = threadIdx.x;
    const int gt = cta*TPB + tid, GT = NCTA*TPB;

    // ---------------- init (every launch: deterministic) ----------------
    for (int i = gt; i < 8*Fc; i += GT) g_state[i] = 0.0f;   // wave + psiy bufs
    if (gt < NCTA) g_step[gt] = 0u;                          // reset step counters

    for (int i = gt; i < NP; i += GT) {
        float fi = (float)i;
        float frac = fmaxf((float)PADc - fi, fi - (float)(NP - PADc - 1)) / (float)PMLc;
        frac = fminf(fmaxf(frac, 0.0f), 1.0f);
        float smax = 3.0f * 4000.0f * logf(1000.0f) / (2.0f * (float)PMLc * Hc);
        float sig  = smax * frac * frac;
        float alp  = 3.14159265358979f * 25.0f * (1.0f - frac);
        float bb   = expf(-(sig + alp) * DTc);
        g_b[i] = bb;
        g_a[i] = sig / (sig + alp + 1e-9f) * (bb - 1.0f);
    }

    for (int i = gt; i < NP*NP; i += GT) {
        int y = i / NP, x = i - y*NP;
        int vy = min(max(y - PADc, 0), NYg - 1);
        int vx = min(max(x - PADc, 0), NYg - 1);
        float vv = v[vy*NYg + vx];
        g_state[8*Fc + IDX(y,x)] = vv * vv * (DTc*DTc);
    }

    const int shot = cta / CPS;
    const int pos  = cta % CPS;
    const int y0   = pos * RPC;
    const bool has_up = (pos > 0);
    const bool has_dn = (pos < CPS - 1);

    __shared__ int   sh_key[NSRCc];
    __shared__ float sh_scale[NSRCc];
    __shared__ float psix_s[RPC][SXc];   // persistent psix state (x-guards = 0)
    __shared__ float ws[RPC][SXc];       // current-step wfc owned rows (x-guards = 0)
    __shared__ int   sh_rn;
    __shared__ int   sh_rr2[NRECc];
    __shared__ int   sh_rx[NRECc];
    __shared__ int   sh_ro[NRECc];

    for (int i = tid; i < RPC*SXc; i += TPB) {
        ((float*)psix_s)[i] = 0.0f;
        ((float*)ws)[i] = 0.0f;
    }

    if (tid < NSRCc) {
        const unsigned* w32 = (const unsigned*)sloc;
        bool is64 = true;
        for (int i = 1; i < NSHOTc*NSRCc*2; i += 2)
            if (w32[i] != 0u) { is64 = false; break; }
        int e = (shot*NSRCc + tid) * 2;
        int sy, sx;
        if (is64) { sy = (int)w32[2*e]; sx = (int)w32[2*(e+1)]; }
        else      { const int* w = (const int*)sloc; sy = w[e]; sx = w[e+1]; }
        float vv = v[sy*NYg + sx];
        sh_key[tid]   = ((sy + PADc) << 9) | (sx + PADc);
        sh_scale[tid] = vv * vv * (DTc*DTc);
    }
    if (tid == 0) {
        const unsigned* w32 = (const unsigned*)rloc;
        bool is64 = true;
        for (int i = 1; i < NSHOTc*NRECc*2; i += 2)
            if (w32[i] != 0u) { is64 = false; break; }
        int n = 0;
        for (int rr = 0; rr < NRECc; rr++) {
            int e = (shot*NRECc + rr) * 2;
            int ry, rx;
            if (is64) { ry = (int)w32[2*e]; rx = (int)w32[2*(e+1)]; }
            else      { const int* w = (const int*)rloc; ry = w[e]; rx = w[e+1]; }
            int yp = ry + PADc;
            if (yp >= y0 && yp < y0 + RPC) {
                sh_rr2[n] = yp - y0;
                sh_rx[n]  = rx + PADc;
                sh_ro[n]  = shot*NRECc + rr;
                n++;
            }
        }
        sh_rn = n;
    }

    gbar(cta, 1u);   // init (incl. g_step resets) visible everywhere

    // ---------------- per-thread setup ----------------
    float* wbase  = g_state + shot*4*Fc;
    float* pybase = wbase + 2*Fc;
    const float* v2 = g_state + 8*Fc;
    const float* amp_s = amp + shot*NSRCc*NTc;

    const float iH  = 1.0f / Hc;
    const float iH2 = 1.0f / (Hc*Hc);
    const float C1A =  0.66666666666666666f, C1B = -0.08333333333333333f;
    const float C2A =  1.33333333333333333f, C2B = -0.08333333333333333f, C2C = -2.5f;

    const int  x   = tid;
    const bool act = (tid < NP);

    float ayr[HR], byr[HR];
    #pragma unroll
    for (int r = 0; r < HR; r++) {
        int y = y0 - 2 + r;
        bool in = (y >= 0 && y < NP);
        ayr[r] = in ? g_a[y] : 0.0f;
        byr[r] = in ? g_b[y] : 0.0f;
    }
    const float axv = act ? g_a[x] : 0.0f;
    const float bxv = act ? g_b[x] : 0.0f;

    bool srow[RPC];
    #pragma unroll
    for (int r2 = 0; r2 < RPC; r2++) {
        bool s = false;
        #pragma unroll
        for (int j = 0; j < NSRCc; j++) s = s || ((sh_key[j] >> 9) == (y0 + r2));
        srow[r2] = s;
    }
    const int nrec = sh_rn;

    float psr[RPC], zyr[RPC], zxr[RPC], wold[RPC];
    #pragma unroll
    for (int r2 = 0; r2 < RPC; r2++) { psr[r2]=0.f; zyr[r2]=0.f; zxr[r2]=0.f; wold[r2]=0.f; }

    int cur = 0;

    // ---------------- time loop: neighbor-only synchronization ----------------
    // Before step t: wait g_step[nbr] >= t (nbr completed step t-1). This
    // guarantees both (a) nbr's step t-1 halo data is globally visible, and
    // (b) nbr is done reading the double-buffer half this step overwrites.
    for (int t = 0; t < NTc; t++) {
        const float* wfc = wbase + cur*Fc;
        float*       wst = wbase + (cur^1)*Fc;
        const int pb = t & 1;
        const float* pyold = pybase + (pb^1)*Fc;
        float*       pynew = pybase + pb*Fc;

        float c[CR];
        // Pre-wait: own rows of wfc (written by this CTA last step — no dependency)
        if (act) {
            #pragma unroll
            for (int k = 4; k < 4 + RPC; k++)
                c[k] = __ldcg(wfc + IDX(y0 - 4 + k, x));
        }

        if (tid == 0) {
            if (has_up) while ((int)ld_rlx(&g_step[cta-1]) < t) { }
            if (has_dn) while ((int)ld_rlx(&g_step[cta+1]) < t) { }
            fence_gpu();   // acquire
        }
        __syncthreads();

        float py[HR], poh[4];
        if (act) {
            // Halo rows of wfc (neighbor's step t-1 output)
            #pragma unroll
            for (int k = 0; k < 4; k++)
                c[k] = __ldcg(wfc + IDX(y0 - 4 + k, x));
            #pragma unroll
            for (int k = 4 + RPC; k < CR; k++)
                c[k] = __ldcg(wfc + IDX(y0 - 4 + k, x));
            // psiy halo (only nonzero inside PML bands: a==0 => psiy === 0)
            poh[0] = (ayr[0]    != 0.0f) ? __ldcg(pyold + IDX(y0-2,     x)) : 0.0f;
            poh[1] = (ayr[1]    != 0.0f) ? __ldcg(pyold + IDX(y0-1,     x)) : 0.0f;
            poh[2] = (ayr[HR-2] != 0.0f) ? __ldcg(pyold + IDX(y0+RPC,   x)) : 0.0f;
            poh[3] = (ayr[HR-1] != 0.0f) ? __ldcg(pyold + IDX(y0+RPC+1, x)) : 0.0f;

            // psiy update for 9 rows (owned + recomputed halo)
            #pragma unroll
            for (int r = 0; r < HR; r++) {
                int y = y0 - 2 + r;
                float dwdy = (C1A*(c[r+3]-c[r+1]) + C1B*(c[r+4]-c[r])) * iH;
                float po;
                if (r == 0) po = poh[0];
                else if (r == 1) po = poh[1];
                else if (r == HR-2) po = poh[2];
                else if (r == HR-1) po = poh[3];
                else po = psr[r-2];
                float pn = byr[r]*po + ayr[r]*dwdy;
                if (y < 0 || y >= NP) pn = 0.0f;
                py[r] = pn;
            }
            #pragma unroll
            for (int r2 = 0; r2 < RPC; r2++) {
                psr[r2] = py[r2+2];
                if (ayr[r2+2] != 0.0f)                 // psiy==0 outside PML
                    pynew[IDX(y0 + r2, x)] = py[r2+2];
                ws[r2][x+4] = c[r2+4];                 // stage owned wfc row to smem
            }
        }
        __syncthreads();   // ws ready for x-taps

        float s1[RPC], s2[RPC], cen[RPC];
        if (act) {
            #pragma unroll
            for (int r2 = 0; r2 < RPC; r2++) {
                int m = r2 + 4;
                float b1 = ws[r2][x+3], b2 = ws[r2][x+5];
                float b3 = ws[r2][x+2], b4 = ws[r2][x+6];
                float d2y  = (C2C*c[m] + C2A*(c[m-1]+c[m+1]) + C2B*(c[m-2]+c[m+2])) * iH2;
                float d2x  = (C2C*c[m] + C2A*(b1+b2)       + C2B*(b3+b4))         * iH2;
                float dwdx = (C1A*(b2-b1) + C1B*(b4-b3)) * iH;
                float dpy  = (C1A*(py[r2+3]-py[r2+1]) + C1B*(py[r2+4]-py[r2])) * iH;
                float pxn  = bxv*psix_s[r2][x+4] + axv*dwdx;
                psix_s[r2][x+4] = pxn;
                s1[r2] = d2y + dpy;
                s2[r2] = d2x;
                cen[r2] = c[m];
            }
        }
        __syncthreads();   // psix taps ready

        if (act) {
            #pragma unroll
            for (int r2 = 0; r2 < RPC; r2++) {
                int y = y0 + r2;
                int p = IDX(y, x);
                float dpx = (C1A*(psix_s[r2][x+5]-psix_s[r2][x+3])
                           + C1B*(psix_s[r2][x+6]-psix_s[r2][x+2])) * iH;
                float ayv = ayr[r2+2], byv = byr[r2+2];
                float zyv = byv*zyr[r2] + ayv*s1[r2];             zyr[r2] = zyv;
                float zxv = bxv*zxr[r2] + axv*(s2[r2] + dpx);     zxr[r2] = zxv;
                float lap = s1[r2] + s2[r2] + dpx + zyv + zxv;
                float wnew = 2.0f*cen[r2] - wold[r2] + v2[p]*lap;
                if (srow[r2]) {
                    int key = (y << 9) | x;
                    #pragma unroll
                    for (int j = 0; j < NSRCc; j++)
                        if (sh_key[j] == key) wnew += sh_scale[j] * amp_s[j*NTc + t];
                }
                wold[r2] = cen[r2];
                wst[p] = wnew;
                for (int j = 0; j < nrec; j++)
                    if (sh_rr2[j] == r2 && sh_rx[j] == x)
                        out[sh_ro[j]*NTc + t] = wnew;
            }
        }
        __syncthreads();   // all stores issued

        if (tid == 0) {
            fence_gpu();                               // release this CTA's step
            st_rlx(&g_step[cta], (unsigned)(t + 1));
        }
        cur ^= 1;
    }
}

extern "C" void kernel_launch(void* const* d_in, const int* in_sizes, int n_in,
                              void* d_out, int out_size)
{
    const float* v    = (const float*)d_in[0];
    const float* amp  = (const float*)d_in[1];
    const void*  sloc = d_in[2];
    const void*  rloc = d_in[3];
    wave_kernel<<<NCTA, TPB>>>(v, amp, sloc, rloc, (float*)d_out);
}

// round 7
// speedup vs baseline: 1.2355x; 1.2355x over previous
#include <cuda_runtime.h>
#include <math.h>

// Problem constants
#define NYg    256
#define PMLc   20
#define PADc   22          // PML + FD_PAD
#define NP     300         // NYP == NXP
#define SXc    320         // padded row stride (floats)
#define Gc     4           // zero guard ring width
#define ARc    (NP + 2*Gc) // 308 rows allocated
#define Fc     (ARc*SXc)   // floats per field = 98560
#define NTc    250
#define NSHOTc 2
#define NSRCc  8
#define NRECc  64

#define DTc 0.0005f
#define Hc  5.0f

// Persistent-kernel config
#define NCTA 120
#define TPB  320
#define CPS  (NCTA/NSHOTc)  // 60 CTAs per shot
#define RPC  (NP/CPS)       // 5 rows per CTA
#define HR   (RPC+4)        // 9 psiy rows (owned + 2 halo each side)
#define CR   (RPC+8)        // 13 wfc column rows

// Per-shot fields: w0,w1,py0,py1 (psix in smem, zeta/wfm in regs). v2 -> field 8
__device__ float g_state[9*Fc];
__device__ float g_a[NP];
__device__ float g_b[NP];
__device__ unsigned g_arr[NCTA];   // arrival mailboxes (1 writer, 1 reader each)
__device__ unsigned g_go[NCTA];    // release mailboxes (1 writer, 1 reader each)

__device__ __forceinline__ int IDX(int y, int x) { return (y+Gc)*SXc + (x+Gc); }

__device__ __forceinline__ unsigned ld_acq(const unsigned* p) {
    unsigned v;
    asm volatile("ld.acquire.gpu.u32 %0, [%1];" : "=r"(v) : "l"(p));
    return v;
}
__device__ __forceinline__ void st_rel(unsigned* p, unsigned v) {
    asm volatile("st.release.gpu.u32 [%0], %1;" :: "l"(p), "r"(v) : "memory");
}

// Grid barrier with fully-distributed mailboxes: every polled cache line has
// exactly ONE reader thread and ONE writer thread -> no L2 same-line
// serialization (the R3 single-sense-line design serialized 119 concurrent
// pollers at ~30cyc each on one LTS slice, dominating the step time).
// st.release / ld.acquire after __syncthreads is the standard cooperative
// groups grid.sync ordering pattern (release covers the CTA's prior writes).
// Phase equality is replay-safe: stale values from a prior launch equal only
// the FINAL phase; aliasing can therefore only affect the last barrier, after
// which no data is read.
__device__ __forceinline__ void gbar(int cta, unsigned ph) {
    __syncthreads();
    if (cta == 0) {
        if (threadIdx.x >= 1 && threadIdx.x < NCTA) {
            while (ld_acq(&g_arr[threadIdx.x]) != ph) { }
        }
        __syncthreads();                 // all arrivals observed by CTA 0
        if (threadIdx.x >= 1 && threadIdx.x < NCTA) {
            st_rel(&g_go[threadIdx.x], ph);   // independent per-CTA releases
        }
        __syncthreads();
    } else {
        if (threadIdx.x == 0) {
            st_rel(&g_arr[cta], ph);     // release this CTA's writes
            while (ld_acq(&g_go[cta]) != ph) { }
        }
        __syncthreads();
    }
}

extern "C" __global__ void __launch_bounds__(TPB)
wave_kernel(const float* __restrict__ v,
            const float* __restrict__ amp,
            const void*  __restrict__ sloc,
            const void*  __restrict__ rloc,
            float* __restrict__ out)
{
    const int cta = blockIdx.x, tid = threadIdx.x;
    const int gt = cta*TPB + tid, GT = NCTA*TPB;

    // ---------------- init (every launch: deterministic) ----------------
    for (int i = gt; i < 8*Fc; i += GT) g_state[i] = 0.0f;   // wave + psiy bufs

    for (int i = gt; i < NP; i += GT) {
        float fi = (float)i;
        float frac = fmaxf((float)PADc - fi, fi - (float)(NP - PADc - 1)) / (float)PMLc;
        frac = fminf(fmaxf(frac, 0.0f), 1.0f);
        float smax = 3.0f * 4000.0f * logf(1000.0f) / (2.0f * (float)PMLc * Hc);
        float sig  = smax * frac * frac;
        float alp  = 3.14159265358979f * 25.0f * (1.0f - frac);
        float bb   = expf(-(sig + alp) * DTc);
        g_b[i] = bb;
        g_a[i] = sig / (sig + alp + 1e-9f) * (bb - 1.0f);
    }

    for (int i = gt; i < NP*NP; i += GT) {
        int y = i / NP, x = i - y*NP;
        int vy = min(max(y - PADc, 0), NYg - 1);
        int vx = min(max(x - PADc, 0), NYg - 1);
        float vv = v[vy*NYg + vx];
        g_state[8*Fc + IDX(y,x)] = vv * vv * (DTc*DTc);
    }

    const int shot = cta / CPS;
    const int y0   = (cta % CPS) * RPC;

    __shared__ int   sh_key[NSRCc];
    __shared__ float sh_scale[NSRCc];
    __shared__ float psix_s[RPC][SXc];   // persistent psix state (x-guards = 0)
    __shared__ int   sh_rn;
    __shared__ int   sh_rr2[NRECc];
    __shared__ int   sh_rx[NRECc];
    __shared__ int   sh_ro[NRECc];

    for (int i = tid; i < RPC*SXc; i += TPB) ((float*)psix_s)[i] = 0.0f;

    if (tid < NSRCc) {
        const unsigned* w32 = (const unsigned*)sloc;
        bool is64 = true;
        for (int i = 1; i < NSHOTc*NSRCc*2; i += 2)
            if (w32[i] != 0u) { is64 = false; break; }
        int e = (shot*NSRCc + tid) * 2;
        int sy, sx;
        if (is64) { sy = (int)w32[2*e]; sx = (int)w32[2*(e+1)]; }
        else      { const int* w = (const int*)sloc; sy = w[e]; sx = w[e+1]; }
        float vv = v[sy*NYg + sx];
        sh_key[tid]   = ((sy + PADc) << 9) | (sx + PADc);
        sh_scale[tid] = vv * vv * (DTc*DTc);
    }
    if (tid == 0) {
        const unsigned* w32 = (const unsigned*)rloc;
        bool is64 = true;
        for (int i = 1; i < NSHOTc*NRECc*2; i += 2)
            if (w32[i] != 0u) { is64 = false; break; }
        int n = 0;
        for (int rr = 0; rr < NRECc; rr++) {
            int e = (shot*NRECc + rr) * 2;
            int ry, rx;
            if (is64) { ry = (int)w32[2*e]; rx = (int)w32[2*(e+1)]; }
            else      { const int* w = (const int*)rloc; ry = w[e]; rx = w[e+1]; }
            int yp = ry + PADc;
            if (yp >= y0 && yp < y0 + RPC) {
                sh_rr2[n] = yp - y0;
                sh_rx[n]  = rx + PADc;
                sh_ro[n]  = shot*NRECc + rr;
                n++;
            }
        }
        sh_rn = n;
    }

    unsigned ph = 0;
    gbar(cta, ++ph);   // init visible everywhere

    // ---------------- per-thread setup ----------------
    float* wbase  = g_state + shot*4*Fc;
    float* pybase = wbase + 2*Fc;
    const float* v2 = g_state + 8*Fc;
    const float* amp_s = amp + shot*NSRCc*NTc;

    const float iH  = 1.0f / Hc;
    const float iH2 = 1.0f / (Hc*Hc);
    const float C1A =  0.66666666666666666f, C1B = -0.08333333333333333f;
    const float C2A =  1.33333333333333333f, C2B = -0.08333333333333333f, C2C = -2.5f;

    const int  x   = tid;
    const bool act = (tid < NP);

    float ayr[HR], byr[HR];
    #pragma unroll
    for (int r = 0; r < HR; r++) {
        int y = y0 - 2 + r;
        bool in = (y >= 0 && y < NP);
        ayr[r] = in ? g_a[y] : 0.0f;
        byr[r] = in ? g_b[y] : 0.0f;
    }
    const float axv = act ? g_a[x] : 0.0f;
    const float bxv = act ? g_b[x] : 0.0f;

    bool srow[RPC];
    #pragma unroll
    for (int r2 = 0; r2 < RPC; r2++) {
        bool s = false;
        #pragma unroll
        for (int j = 0; j < NSRCc; j++) s = s || ((sh_key[j] >> 9) == (y0 + r2));
        srow[r2] = s;
    }
    const int nrec = sh_rn;

    float psr[RPC], zyr[RPC], zxr[RPC], wold[RPC];
    #pragma unroll
    for (int r2 = 0; r2 < RPC; r2++) { psr[r2]=0.f; zyr[r2]=0.f; zxr[r2]=0.f; wold[r2]=0.f; }

    int cur = 0;

    // ---------------- time loop: ONE grid barrier per step ----------------
    for (int t = 0; t < NTc; t++) {
        const float* wfc = wbase + cur*Fc;
        float*       wst = wbase + (cur^1)*Fc;
        const int pb = t & 1;
        const float* pyold = pybase + (pb^1)*Fc;
        float*       pynew = pybase + pb*Fc;

        float s1[RPC], s2[RPC], cen[RPC];

        if (act) {
            // Column of wfc at this x: rows y0-4 .. y0+8 (13 independent L2 loads)
            float c[CR];
            #pragma unroll
            for (int k = 0; k < CR; k++)
                c[k] = __ldcg(wfc + IDX(y0 - 4 + k, x));
            // psiy halo (psiy == 0 wherever a == 0, by induction from zero init)
            float poh[4];
            poh[0] = (ayr[0]    != 0.0f) ? __ldcg(pyold + IDX(y0-2,     x)) : 0.0f;
            poh[1] = (ayr[1]    != 0.0f) ? __ldcg(pyold + IDX(y0-1,     x)) : 0.0f;
            poh[2] = (ayr[HR-2] != 0.0f) ? __ldcg(pyold + IDX(y0+RPC,   x)) : 0.0f;
            poh[3] = (ayr[HR-1] != 0.0f) ? __ldcg(pyold + IDX(y0+RPC+1, x)) : 0.0f;

            // psiy update for 9 rows (owned + recomputed halo)
            float py[HR];
            #pragma unroll
            for (int r = 0; r < HR; r++) {
                int y = y0 - 2 + r;
                float dwdy = (C1A*(c[r+3]-c[r+1]) + C1B*(c[r+4]-c[r])) * iH;
                float po;
                if (r == 0) po = poh[0];
                else if (r == 1) po = poh[1];
                else if (r == HR-2) po = poh[2];
                else if (r == HR-1) po = poh[3];
                else po = psr[r-2];
                float pn = byr[r]*po + ayr[r]*dwdy;
                if (y < 0 || y >= NP) pn = 0.0f;
                py[r] = pn;
            }
            #pragma unroll
            for (int r2 = 0; r2 < RPC; r2++) {
                psr[r2] = py[r2+2];
                if (ayr[r2+2] != 0.0f)         // skip store where psiy === 0
                    pynew[IDX(y0 + r2, x)] = py[r2+2];
            }

            // Owned rows: second derivatives, dpsiydy, psix update (smem)
            #pragma unroll
            for (int r2 = 0; r2 < RPC; r2++) {
                int m = r2 + 4;
                int p = IDX(y0 + r2, x);
                float b1 = wfc[p-1], b2 = wfc[p+1], b3 = wfc[p-2], b4 = wfc[p+2];
                float d2y  = (C2C*c[m] + C2A*(c[m-1]+c[m+1]) + C2B*(c[m-2]+c[m+2])) * iH2;
                float d2x  = (C2C*c[m] + C2A*(b1+b2)       + C2B*(b3+b4))         * iH2;
                float dwdx = (C1A*(b2-b1) + C1B*(b4-b3)) * iH;
                float dpy  = (C1A*(py[r2+3]-py[r2+1]) + C1B*(py[r2+4]-py[r2])) * iH;
                float pxn  = bxv*psix_s[r2][x+4] + axv*dwdx;
                psix_s[r2][x+4] = pxn;
                s1[r2] = d2y + dpy;
                s2[r2] = d2x;
                cen[r2] = c[m];
            }
        }
        __syncthreads();   // psix taps ready

        if (act) {
            #pragma unroll
            for (int r2 = 0; r2 < RPC; r2++) {
                int y = y0 + r2;
                int p = IDX(y, x);
                float dpx = (C1A*(psix_s[r2][x+5]-psix_s[r2][x+3])
                           + C1B*(psix_s[r2][x+6]-psix_s[r2][x+2])) * iH;
                float ayv = ayr[r2+2], byv = byr[r2+2];
                float zyv = byv*zyr[r2] + ayv*s1[r2];             zyr[r2] = zyv;
                float zxv = bxv*zxr[r2] + axv*(s2[r2] + dpx);     zxr[r2] = zxv;
                float lap = s1[r2] + s2[r2] + dpx + zyv + zxv;
                float wnew = 2.0f*cen[r2] - wold[r2] + v2[p]*lap;
                if (srow[r2]) {
                    int key = (y << 9) | x;
                    #pragma unroll
                    for (int j = 0; j < NSRCc; j++)
                        if (sh_key[j] == key) wnew += sh_scale[j] * amp_s[j*NTc + t];
                }
                wold[r2] = cen[r2];
                wst[p] = wnew;
                for (int j = 0; j < nrec; j++)
                    if (sh_rr2[j] == r2 && sh_rx[j] == x)
                        out[sh_ro[j]*NTc + t] = wnew;
            }
        }

        gbar(cta, ++ph);   // step complete everywhere
        cur ^= 1;
    }
}

extern "C" void kernel_launch(void* const* d_in, const int* in_sizes, int n_in,
                              void* d_out, int out_size)
{
    const float* v    = (const float*)d_in[0];
    const float* amp  = (const float*)d_in[1];
    const void*  sloc = d_in[2];
    const void*  rloc = d_in[3];
    wave_kernel<<<NCTA, TPB>>>(v, amp, sloc, rloc, (float*)d_out);
}

// round 9
// speedup vs baseline: 1.4935x; 1.2088x over previous
#include <cuda_runtime.h>
#include <math.h>

// Problem constants
#define NYg    256
#define PMLc   20
#define PADc   22          // PML + FD_PAD
#define NP     300         // NYP == NXP
#define SXc    320         // padded row stride (floats)
#define Gc     4           // zero guard ring width
#define ARc    (NP + 2*Gc) // 308 rows allocated
#define Fc     (ARc*SXc)   // floats per field = 98560
#define NTc    250
#define NSHOTc 2
#define NSRCc  8
#define NRECc  64

#define DTc 0.0005f
#define Hc  5.0f

// Persistent-kernel config
#define NCTA 120
#define TPB  640            // two 320-thread row-groups per CTA
#define CPS  (NCTA/NSHOTc)  // 60 CTAs per shot
#define RPC  (NP/CPS)       // 5 rows per CTA
#define RN_MAX 3            // max owned rows per group (g0:3, g1:2)
#define PR_MAX (RN_MAX+4)   // max psiy rows per group (7)
#define CN_MAX (RN_MAX+8)   // max wfc column rows per group (11)

// Per-shot fields: w0,w1,py0,py1 (psix in smem, zeta/wfm in regs). v2 -> field 8
__device__ float g_state[9*Fc];
__device__ float g_a[NP];
__device__ float g_b[NP];
// Mailboxes padded to 128B lines
__device__ unsigned g_arr[NCTA*32];
__device__ unsigned g_go[NCTA*32];

__device__ __forceinline__ int IDX(int y, int x) { return (y+Gc)*SXc + (x+Gc); }

__device__ __forceinline__ unsigned ld_acq(const unsigned* p) {
    unsigned v;
    asm volatile("ld.acquire.gpu.u32 %0, [%1];" : "=r"(v) : "l"(p));
    return v;
}
__device__ __forceinline__ void st_rel(unsigned* p, unsigned v) {
    asm volatile("st.release.gpu.u32 [%0], %1;" :: "l"(p), "r"(v) : "memory");
}

// Grid barrier (distributed mailboxes, one 128B line each).
// Phase equality is replay-safe: stale values from a prior launch equal only
// the FINAL phase, which can alias only the last barrier (after which no data
// is read).
__device__ __forceinline__ void gbar(int cta, unsigned ph) {
    __syncthreads();
    if (cta == 0) {
        if (threadIdx.x >= 1 && threadIdx.x < NCTA) {
            while (ld_acq(&g_arr[threadIdx.x*32]) != ph) { }
        }
        __syncthreads();
        if (threadIdx.x >= 1 && threadIdx.x < NCTA) {
            st_rel(&g_go[threadIdx.x*32], ph);
        }
        __syncthreads();
    } else {
        if (threadIdx.x == 0) {
            st_rel(&g_arr[cta*32], ph);
            while (ld_acq(&g_go[cta*32]) != ph) { }
        }
        __syncthreads();
    }
}

extern "C" __global__ void __launch_bounds__(TPB, 1)
wave_kernel(const float* __restrict__ v,
            const float* __restrict__ amp,
            const void*  __restrict__ sloc,
            const void*  __restrict__ rloc,
            float* __restrict__ out)
{
    const int cta = blockIdx.x, tid = threadIdx.x;
    const int gt = cta*TPB + tid, GT = NCTA*TPB;

    // ---------------- init (every launch: deterministic) ----------------
    for (int i = gt; i < 8*Fc; i += GT) g_state[i] = 0.0f;

    for (int i = gt; i < NP; i += GT) {
        float fi = (float)i;
        float frac = fmaxf((float)PADc - fi, fi - (float)(NP - PADc - 1)) / (float)PMLc;
        frac = fminf(fmaxf(frac, 0.0f), 1.0f);
        float smax = 3.0f * 4000.0f * logf(1000.0f) / (2.0f * (float)PMLc * Hc);
        float sig  = smax * frac * frac;
        float alp  = 3.14159265358979f * 25.0f * (1.0f - frac);
        float bb   = expf(-(sig + alp) * DTc);
        g_b[i] = bb;
        g_a[i] = sig / (sig + alp + 1e-9f) * (bb - 1.0f);
    }

    for (int i = gt; i < NP*NP; i += GT) {
        int y = i / NP, x = i - y*NP;
        int vy = min(max(y - PADc, 0), NYg - 1);
        int vx = min(max(x - PADc, 0), NYg - 1);
        float vv = v[vy*NYg + vx];
        g_state[8*Fc + IDX(y,x)] = vv * vv * (DTc*DTc);
    }

    const int shot = cta / CPS;
    const int y0   = (cta % CPS) * RPC;

    // Row-group split: g0 -> local rows 0..2, g1 -> local rows 3..4
    const int g   = (tid >= 320) ? 1 : 0;
    const int x   = tid - g*320;
    const int RLO = g ? 3 : 0;
    const int RN  = g ? 2 : 3;
    const int yb  = y0 + RLO;          // first owned row of this group
    const int PR  = RN + 4;            // psiy rows (yb-2 .. yb+RN+1)
    const int CN  = RN + 8;            // wfc column rows (yb-4 .. yb+RN+3)

    __shared__ int   sh_key[NSRCc];
    __shared__ float sh_scale[NSRCc];
    __shared__ float psix_s[RPC][SXc]; // persistent psix (absolute local rows)
    __shared__ int   sh_rn;
    __shared__ int   sh_rr2[NRECc];    // local row (0..4) of receiver
    __shared__ int   sh_rx[NRECc];
    __shared__ int   sh_ro[NRECc];

    for (int i = tid; i < RPC*SXc; i += TPB) ((float*)psix_s)[i] = 0.0f;

    if (tid < NSRCc) {
        const unsigned* w32 = (const unsigned*)sloc;
        bool is64 = true;
        for (int i = 1; i < NSHOTc*NSRCc*2; i += 2)
            if (w32[i] != 0u) { is64 = false; break; }
        int e = (shot*NSRCc + tid) * 2;
        int sy, sx;
        if (is64) { sy = (int)w32[2*e]; sx = (int)w32[2*(e+1)]; }
        else      { const int* w = (const int*)sloc; sy = w[e]; sx = w[e+1]; }
        float vv = v[sy*NYg + sx];
        sh_key[tid]   = ((sy + PADc) << 9) | (sx + PADc);
        sh_scale[tid] = vv * vv * (DTc*DTc);
    }
    if (tid == 0) {
        const unsigned* w32 = (const unsigned*)rloc;
        bool is64 = true;
        for (int i = 1; i < NSHOTc*NRECc*2; i += 2)
            if (w32[i] != 0u) { is64 = false; break; }
        int n = 0;
        for (int rr = 0; rr < NRECc; rr++) {
            int e = (shot*NRECc + rr) * 2;
            int ry, rx;
            if (is64) { ry = (int)w32[2*e]; rx = (int)w32[2*(e+1)]; }
            else      { const int* w = (const int*)rloc; ry = w[e]; rx = w[e+1]; }
            int yp = ry + PADc;
            if (yp >= y0 && yp < y0 + RPC) {
                sh_rr2[n] = yp - y0;
                sh_rx[n]  = rx + PADc;
                sh_ro[n]  = shot*NRECc + rr;
                n++;
            }
        }
        sh_rn = n;
    }

    unsigned ph = 0;
    gbar(cta, ++ph);   // init visible everywhere

    // ---------------- per-thread setup ----------------
    float* wbase  = g_state + shot*4*Fc;
    float* pybase = wbase + 2*Fc;
    const float* v2 = g_state + 8*Fc;
    const float* amp_s = amp + shot*NSRCc*NTc;

    const float iH  = 1.0f / Hc;
    const float iH2 = 1.0f / (Hc*Hc);
    const float C1A =  0.66666666666666666f, C1B = -0.08333333333333333f;
    const float C2A =  1.33333333333333333f, C2B = -0.08333333333333333f, C2C = -2.5f;

    const bool act = (x < NP);

    // PML coefs for psiy rows (yb-2+r), r < PR
    float ayr[PR_MAX], byr[PR_MAX];
    #pragma unroll
    for (int r = 0; r < PR_MAX; r++) {
        int y = yb - 2 + r;
        bool in = (r < PR) && (y >= 0 && y < NP);
        ayr[r] = in ? g_a[y] : 0.0f;
        byr[r] = in ? g_b[y] : 0.0f;
    }
    const float axv = act ? g_a[x] : 0.0f;
    const float bxv = act ? g_b[x] : 0.0f;

    bool srow[RN_MAX];
    #pragma unroll
    for (int r2 = 0; r2 < RN_MAX; r2++) {
        bool s = false;
        #pragma unroll
        for (int j = 0; j < NSRCc; j++) s = s || ((sh_key[j] >> 9) == (yb + r2));
        srow[r2] = (r2 < RN) && s;
    }
    const int nrec = sh_rn;

    float psr[RN_MAX], zyr[RN_MAX], zxr[RN_MAX], wold[RN_MAX];
    #pragma unroll
    for (int r2 = 0; r2 < RN_MAX; r2++) { psr[r2]=0.f; zyr[r2]=0.f; zxr[r2]=0.f; wold[r2]=0.f; }

    int cur = 0;

    // ---------------- time loop: ONE grid barrier per step ----------------
    for (int t = 0; t < NTc; t++) {
        const float* wfc = wbase + cur*Fc;
        float*       wst = wbase + (cur^1)*Fc;
        const int pb = t & 1;
        const float* pyold = pybase + (pb^1)*Fc;
        float*       pynew = pybase + pb*Fc;

        float s1[RN_MAX], s2[RN_MAX], cen[RN_MAX];

        if (act) {
            // Column of wfc: rows yb-4 .. yb+RN+3 (<=11 independent L2 loads)
            float c[CN_MAX];
            #pragma unroll
            for (int k = 0; k < CN_MAX; k++)
                if (k < CN) c[k] = __ldcg(wfc + IDX(yb - 4 + k, x));
            // psiy halo: rows yb-2, yb-1, yb+RN, yb+RN+1 — owned by neighbor CTA
            // or the other group; stored to pyold each step wherever a != 0
            // (psiy == 0 where a == 0, by induction from zero init).
            float poh[4];
            poh[0] = (ayr[0]    != 0.0f) ? __ldcg(pyold + IDX(yb-2,    x)) : 0.0f;
            poh[1] = (ayr[1]    != 0.0f) ? __ldcg(pyold + IDX(yb-1,    x)) : 0.0f;
            poh[2] = (ayr[PR-2] != 0.0f) ? __ldcg(pyold + IDX(yb+RN,   x)) : 0.0f;
            poh[3] = (ayr[PR-1] != 0.0f) ? __ldcg(pyold + IDX(yb+RN+1, x)) : 0.0f;

            // psiy update (owned + recomputed halo rows)
            float py[PR_MAX];
            #pragma unroll
            for (int r = 0; r < PR_MAX; r++) {
                if (r < PR) {
                    int y = yb - 2 + r;
                    float dwdy = (C1A*(c[r+3]-c[r+1]) + C1B*(c[r+4]-c[r])) * iH;
                    float po;
                    if (r == 0) po = poh[0];
                    else if (r == 1) po = poh[1];
                    else if (r == PR-2) po = poh[2];
                    else if (r == PR-1) po = poh[3];
                    else po = psr[r-2];
                    float pn = byr[r]*po + ayr[r]*dwdy;
                    if (y < 0 || y >= NP) pn = 0.0f;
                    py[r] = pn;
                }
            }
            #pragma unroll
            for (int r2 = 0; r2 < RN_MAX; r2++) {
                if (r2 < RN) {
                    psr[r2] = py[r2+2];
                    if (ayr[r2+2] != 0.0f)
                        pynew[IDX(yb + r2, x)] = py[r2+2];
                }
            }

            // Owned rows: second derivatives, dpsiydy, psix update (smem)
            #pragma unroll
            for (int r2 = 0; r2 < RN_MAX; r2++) {
                if (r2 < RN) {
                    int m = r2 + 4;
                    int p = IDX(yb + r2, x);
                    float b1 = wfc[p-1], b2 = wfc[p+1], b3 = wfc[p-2], b4 = wfc[p+2];
                    float d2y  = (C2C*c[m] + C2A*(c[m-1]+c[m+1]) + C2B*(c[m-2]+c[m+2])) * iH2;
                    float d2x  = (C2C*c[m] + C2A*(b1+b2)       + C2B*(b3+b4))         * iH2;
                    float dwdx = (C1A*(b2-b1) + C1B*(b4-b3)) * iH;
                    float dpy  = (C1A*(py[r2+3]-py[r2+1]) + C1B*(py[r2+4]-py[r2])) * iH;
                    float pxn  = bxv*psix_s[RLO+r2][x+4] + axv*dwdx;
                    psix_s[RLO+r2][x+4] = pxn;
                    s1[r2] = d2y + dpy;
                    s2[r2] = d2x;
                    cen[r2] = c[m];
                }
            }
        }
        __syncthreads();   // psix x-taps ready

        if (act) {
            #pragma unroll
            for (int r2 = 0; r2 < RN_MAX; r2++) {
                if (r2 < RN) {
                    int y = yb + r2;
                    int p = IDX(y, x);
                    float dpx = (C1A*(psix_s[RLO+r2][x+5]-psix_s[RLO+r2][x+3])
                               + C1B*(psix_s[RLO+r2][x+6]-psix_s[RLO+r2][x+2])) * iH;
                    float ayv = ayr[r2+2], byv = byr[r2+2];
                    float zyv = byv*zyr[r2] + ayv*s1[r2];             zyr[r2] = zyv;
                    float zxv = bxv*zxr[r2] + axv*(s2[r2] + dpx);     zxr[r2] = zxv;
                    float lap = s1[r2] + s2[r2] + dpx + zyv + zxv;
                    float wnew = 2.0f*cen[r2] - wold[r2] + v2[p]*lap;
                    if (srow[r2]) {
                        int key = (y << 9) | x;
                        #pragma unroll
                        for (int j = 0; j < NSRCc; j++)
                            if (sh_key[j] == key) wnew += sh_scale[j] * amp_s[j*NTc + t];
                    }
                    wold[r2] = cen[r2];
                    wst[p] = wnew;
                    for (int j = 0; j < nrec; j++)
                        if (sh_rr2[j] == RLO + r2 && sh_rx[j] == x)
                            out[sh_ro[j]*NTc + t] = wnew;
                }
            }
        }

        gbar(cta, ++ph);   // step complete everywhere
        cur ^= 1;
    }
}

extern "C" void kernel_launch(void* const* d_in, const int* in_sizes, int n_in,
                              void* d_out, int out_size)
{
    const float* v    = (const float*)d_in[0];
    const float* amp  = (const float*)d_in[1];
    const void*  sloc = d_in[2];
    const void*  rloc = d_in[3];
    wave_kernel<<<NCTA, TPB>>>(v, amp, sloc, rloc, (float*)d_out);
}